// round 8
// baseline (speedup 1.0000x reference)
#include <cuda_runtime.h>
#include <cstdint>

#define BB 8
#define NN 262144
#define KK 256
#define DD 16
#define CAP 2048
#define MMAX 1024
#define PB_BLOCKS 128          // pass_b blocks per event (2048 rows each)
#define REP_BLOCKS 16          // rep j-chunk blocks per event
#define RCH 64                 // rep j-chunk size

// ---------------- scratch (device globals; zero == reset state) ----------------
__device__ float  g_sum_f [BB][KK];
__device__ int    g_cnt_cp[BB][KK];
__device__ int    g_inst  [BB][KK];
__device__ int    g_first [BB][KK];   // stores max(NN - li); 0 == no CP
__device__ float  g_sd2   [BB][KK];
__device__ float4 g_anchor[BB][KK][4];
__device__ int    g_Mv    [BB];
__device__ int    g_cplist[BB][CAP];
__device__ float  g_scal_f[BB][4];    // 0: sum ce0*~cp, 1: sum ce0*bg, 2: pos_margin, 3: neg_margin
__device__ int    g_scal_i[BB][2];    // 0: n_cp(all), 1: n_bg
__device__ float  g_rep   [BB];
__device__ float4 g_cpemb [BB][MMAX * 4];

// fast sigmoid + softplus: 2 MUFU + FMA-pipe Newton rcp (seed valid on u in (1,2])
__device__ __forceinline__ void fast_sig_sp(float x, float& p, float& ce0) {
    const float t = __expf(-fabsf(x));
    const float u = 1.f + t;
    float y = __fmaf_rn(u, -0.47058824f, 1.4117647f);
    y = y * __fmaf_rn(-u, y, 2.f);
    y = y * __fmaf_rn(-u, y, 2.f);
    ce0 = fmaxf(x, 0.f) + __logf(u);
    p   = (x >= 0.f) ? y : t * y;
}

// ---------------- pass A: full prefetch (12 LDG.128 in flight), grid 64x8 ----------
__global__ void __launch_bounds__(256) pass_a_kernel(
    const float* __restrict__ beta,
    const int* __restrict__ sid,
    const int* __restrict__ cp)
{
    const int b   = blockIdx.y;
    const int tid = threadIdx.x;

    __shared__ float s_f[KK];
    __shared__ int   s_cnt[KK];
    __shared__ int   s_first[KK];
    __shared__ float s_sc[4];
    __shared__ int   s_si[2];

    s_f[tid] = 0.f; s_cnt[tid] = 0; s_first[tid] = 0;
    if (tid < 4) s_sc[tid] = 0.f;
    if (tid < 2) s_si[tid] = 0;
    __syncthreads();

    float ce0n = 0.f, bg = 0.f, pm = 0.f, nm = 0.f;
    int ncp = 0, nbg = 0;

    const size_t ev_base = (size_t)b * NN;
    const int blk_base = blockIdx.x * 4096;

    int4 s4[4], c4[4];
    float4 x4[4];
    #pragma unroll
    for (int it = 0; it < 4; it++) {
        const int li0 = blk_base + it * 1024 + tid * 4;
        s4[it] = *reinterpret_cast<const int4*>(sid + ev_base + li0);
        c4[it] = *reinterpret_cast<const int4*>(cp  + ev_base + li0);
        x4[it] = *reinterpret_cast<const float4*>(beta + ev_base + li0);
    }

    #pragma unroll
    for (int it = 0; it < 4; it++) {
        const int li0 = blk_base + it * 1024 + tid * 4;
        const int   sv[4] = {s4[it].x, s4[it].y, s4[it].z, s4[it].w};
        const int   cv[4] = {c4[it].x, c4[it].y, c4[it].z, c4[it].w};
        const float xv[4] = {x4[it].x, x4[it].y, x4[it].z, x4[it].w};

        #pragma unroll
        for (int j = 0; j < 4; j++) {
            const int   s = sv[j];
            const float x = xv[j];
            float p, ce0;
            fast_sig_sp(x, p, ce0);

            if (cv[j]) {
                ncp++;
                pm += fmaxf(0.8f - p, 0.f);
                if (s >= 0) {
                    const float om = 1.f - p;
                    atomicAdd(&s_f[s], 0.75f * om * om * (ce0 - x));
                    atomicAdd(&s_cnt[s], 1);
                    atomicMax(&s_first[s], NN - (li0 + j));
                    int pos = atomicAdd(&g_Mv[b], 1);
                    if (pos < CAP) g_cplist[b][pos] = li0 + j;
                }
            } else {
                ce0n += ce0;
                nm += fmaxf(p - 0.2f, 0.f);
            }
            if (s == -1) { nbg++; bg += ce0; }
        }
    }

    atomicAdd(&s_sc[0], ce0n);
    atomicAdd(&s_sc[1], bg);
    atomicAdd(&s_sc[2], pm);
    atomicAdd(&s_sc[3], nm);
    atomicAdd(&s_si[0], ncp);
    atomicAdd(&s_si[1], nbg);
    __syncthreads();

    if (s_f[tid] != 0.f) atomicAdd(&g_sum_f[b][tid], s_f[tid]);
    if (s_cnt[tid])      atomicAdd(&g_cnt_cp[b][tid], s_cnt[tid]);
    if (s_first[tid])    atomicMax(&g_first[b][tid], s_first[tid]);
    if (tid < 4) atomicAdd(&g_scal_f[b][tid], s_sc[tid]);
    if (tid < 2) atomicAdd(&g_scal_i[b][tid], s_si[tid]);
}

// ---------------- rep prep (+ anchor gather): one block per event ----------------
__global__ void __launch_bounds__(1024) rep_prep_kernel(const float* __restrict__ embed) {
    const int b   = blockIdx.x;
    const int tid = threadIdx.x;
    __shared__ int sidx[CAP];

    for (int t = tid; t < KK * 4; t += 1024) {
        const int q = t & 3, k = t >> 2;
        const int val = g_first[b][k];
        float4 v = make_float4(0.f, 0.f, 0.f, 0.f);
        if (val > 0) {
            const int fi = NN - val;
            v = reinterpret_cast<const float4*>(embed + ((size_t)b * NN + fi) * DD)[q];
        }
        g_anchor[b][k][q] = v;
    }

    const int Mv   = g_Mv[b];
    const int mcol = min(Mv, CAP);
    const int msel = min(Mv, MMAX);

    for (int i = tid; i < CAP; i += 1024)
        sidx[i] = (i < mcol) ? g_cplist[b][i] : 0x7fffffff;
    __syncthreads();

    if (Mv > MMAX) {   // statistically never; correctness fallback
        for (int ksz = 2; ksz <= CAP; ksz <<= 1) {
            for (int j = ksz >> 1; j > 0; j >>= 1) {
                for (int i = tid; i < CAP; i += 1024) {
                    int ixj = i ^ j;
                    if (ixj > i) {
                        bool up = ((i & ksz) == 0);
                        int a = sidx[i], c = sidx[ixj];
                        if ((a > c) == up) { sidx[i] = c; sidx[ixj] = a; }
                    }
                }
                __syncthreads();
            }
        }
    }

    for (int t = tid; t < msel * 4; t += 1024) {
        const int i = t >> 2, qq = t & 3;
        g_cpemb[b][i * 4 + qq] =
            reinterpret_cast<const float4*>(embed + ((size_t)b * NN + sidx[i]) * DD)[qq];
    }
}

// ---------------- fused: pass_b (bx<128) + repulsion (bx>=128), 512 thr -------------
__global__ void __launch_bounds__(512) fused_kernel(
    const float* __restrict__ embed,
    const int* __restrict__ sid)
{
    const int b   = blockIdx.y;
    const int tid = threadIdx.x;

    if (blockIdx.x < PB_BLOCKS) {
        // ======== pass B: attraction + instance counts ========
        __shared__ float4             sA[KK][4];     // 16 KB
        __shared__ int                ssid[2048];    // 8 KB
        __shared__ unsigned long long spack[KK];     // 2 KB
        __shared__ unsigned char      shc[KK];

        const int lane = tid & 31;
        const int wrp  = tid >> 5;                 // 0..15
        const int g    = lane >> 2;                // 0..7
        const int q    = lane & 3;
        const unsigned gmask = 0xFu << (lane & 28);

        #pragma unroll
        for (int i = tid; i < KK * 4; i += 512)
            sA[i >> 2][i & 3] = g_anchor[b][i >> 2][i & 3];
        if (tid < KK) {
            spack[tid] = 0ull;
            shc[tid] = (g_cnt_cp[b][tid] > 0) ? 1 : 0;
        }

        const size_t ev_base = (size_t)b * NN;
        const int blk_base = blockIdx.x * 2048;
        reinterpret_cast<int4*>(ssid)[tid] =
            reinterpret_cast<const int4*>(sid + ev_base + blk_base)[tid];
        __syncthreads();

        #pragma unroll 4
        for (int it = 0; it < 16; it++) {
            const int rl = it * 128 + wrp * 8 + g;   // local row 0..2047
            const int s = ssid[rl];
            if (s >= 0) {                            // uniform within 4-lane group
                unsigned long long pack = (q == 0) ? (1ull << 44) : 0ull;
                if (shc[s]) {
                    const float4 ev = reinterpret_cast<const float4*>(
                        embed + (ev_base + blk_base + rl) * DD)[q];
                    const float4 av = sA[s][q];
                    const float dx = ev.x - av.x, dy = ev.y - av.y;
                    const float dz = ev.z - av.z, dw = ev.w - av.w;
                    float d2 = dx * dx + dy * dy + dz * dz + dw * dw;
                    d2 += __shfl_xor_sync(gmask, d2, 1);
                    d2 += __shfl_xor_sync(gmask, d2, 2);
                    if (q == 0) pack += __float2ull_rn(d2 * 1048576.f);
                }
                if (q == 0) atomicAdd(&spack[s], pack);
            }
        }
        __syncthreads();
        if (tid < KK) {
            const unsigned long long v = spack[tid];
            if (v) {
                atomicAdd(&g_inst[b][tid], (int)(v >> 44));
                const float ds = (float)(v & ((1ull << 44) - 1ull)) * (1.f / 1048576.f);
                if (ds != 0.f) atomicAdd(&g_sd2[b][tid], ds);
            }
        }
    } else {
        // ======== repulsion: j-chunk (blockIdx.x - 128) ========
        const int j0 = (blockIdx.x - PB_BLOCKS) * RCH;
        const int Mv   = g_Mv[b];
        const int msel = min(Mv, MMAX);
        if (j0 >= msel) return;                    // block-uniform
        const int cnt = min(RCH, msel - j0);

        __shared__ float sj[RCH * DD];             // 4 KB
        __shared__ float red[16];

        for (int t = tid; t < cnt * 4; t += 512) {
            const int j = t >> 2, qq = t & 3;
            reinterpret_cast<float4*>(sj)[j * 4 + qq] = g_cpemb[b][(j0 + j) * 4 + qq];
        }
        __syncthreads();

        float acc = 0.f;
        for (int i = tid; i < msel; i += 512) {
            float myE[DD];
            #pragma unroll
            for (int qq = 0; qq < 4; qq++) {
                const float4 v = g_cpemb[b][i * 4 + qq];
                myE[qq * 4 + 0] = v.x; myE[qq * 4 + 1] = v.y;
                myE[qq * 4 + 2] = v.z; myE[qq * 4 + 3] = v.w;
            }
            #pragma unroll 2
            for (int j = 0; j < cnt; j++) {
                float d2 = 0.f;
                #pragma unroll
                for (int d = 0; d < DD; d++) {
                    const float df = myE[d] - sj[j * DD + d];
                    d2 = __fmaf_rn(df, df, d2);
                }
                acc += __expf(-d2);
            }
        }

        #pragma unroll
        for (int off = 16; off; off >>= 1) acc += __shfl_down_sync(0xffffffff, acc, off);
        if ((tid & 31) == 0) red[tid >> 5] = acc;
        __syncthreads();
        if (tid == 0) {
            float tot = 0.f;
            #pragma unroll
            for (int w = 0; w < 16; w++) tot += red[w];
            atomicAdd(&g_rep[b], tot);
        }
    }
}

// ---------------- finalize (+ state reset for graph replay) ----------------
__global__ void __launch_bounds__(256) finalize_kernel(float* __restrict__ out) {
    const int tid  = threadIdx.x;
    const int lane = tid & 31;
    const int wid  = tid >> 5;
    __shared__ float rw[8], rwf[8], rat[8];
    __shared__ float s_total[1], s_cnt[1];
    if (tid == 0) { s_total[0] = 0.f; s_cnt[0] = 0.f; }
    __syncthreads();

    for (int b = 0; b < BB; b++) {
        const int c    = g_cnt_cp[b][tid];
        const int inst = g_inst[b][tid];
        float w = 0.f, wf = 0.f, at = 0.f;
        if (c > 0) {
            w  = (float)inst;
            wf = w * g_sum_f[b][tid] / fmaxf((float)c, 1.f);
            at = g_sd2[b][tid] / fmaxf((float)inst, 1.f);
        }
        #pragma unroll
        for (int off = 16; off; off >>= 1) {
            w  += __shfl_down_sync(0xffffffff, w,  off);
            wf += __shfl_down_sync(0xffffffff, wf, off);
            at += __shfl_down_sync(0xffffffff, at, off);
        }
        if (lane == 0) { rw[wid] = w; rwf[wid] = wf; rat[wid] = at; }
        __syncthreads();
        if (tid == 0) {
            float sw = 0.f, swf = 0.f, sat = 0.f;
            for (int qq = 0; qq < 8; qq++) { sw += rw[qq]; swf += rwf[qq]; sat += rat[qq]; }
            const float pos_bce = swf / fmaxf(sw, 1.f);

            const float n_cp  = (float)g_scal_i[b][0];
            const float n_bg  = (float)g_scal_i[b][1];
            const float n_ncp = (float)NN - n_cp;
            const float n_val = (float)NN - n_bg;

            const float neg_bce    = (n_ncp > 0.f) ? g_scal_f[b][0] / fmaxf(n_ncp, 1.f) : 0.f;
            const float bg_bce     = (n_bg  > 0.f) ? g_scal_f[b][1] / fmaxf(n_bg,  1.f) : 0.f;
            const float pos_margin = g_scal_f[b][2] / fmaxf(n_cp, 1.f);
            const float neg_margin = (n_ncp > 0.f) ? g_scal_f[b][3] / fmaxf(n_ncp, 1.f) : 0.f;

            const float beta_loss = 10.f * pos_bce + 3.f * neg_bce + 6.f * bg_bce
                                  + 10.f * (pos_margin + neg_margin);

            const int   Mv = g_Mv[b];
            const float fM = (float)Mv;
            const float rep_term = (Mv > 1) ? g_rep[b] / fmaxf(fM * fM, 1.f) : 0.f;

            const float loss = beta_loss + sat + rep_term;

            const bool ok = (n_val > 0.f) && (Mv > 0);
            if (ok) { s_total[0] += loss; s_cnt[0] += 1.f; }
        }
        __syncthreads();
    }
    if (tid == 0)
        out[0] = (s_cnt[0] > 0.f) ? s_total[0] / fmaxf(s_cnt[0], 1.f) : 0.f;

    // reset all scratch so the graph replays deterministically
    __syncthreads();
    #pragma unroll
    for (int b = 0; b < BB; b++) {
        g_sum_f[b][tid]  = 0.f;
        g_cnt_cp[b][tid] = 0;
        g_inst[b][tid]   = 0;
        g_first[b][tid]  = 0;
        g_sd2[b][tid]    = 0.f;
    }
    if (tid < BB) {
        g_Mv[tid]  = 0;
        g_rep[tid] = 0.f;
        #pragma unroll
        for (int j = 0; j < 4; j++) g_scal_f[tid][j] = 0.f;
        g_scal_i[tid][0] = 0; g_scal_i[tid][1] = 0;
    }
}

// ---------------- launch ----------------
extern "C" void kernel_launch(void* const* d_in, const int* in_sizes, int n_in,
                              void* d_out, int out_size)
{
    (void)in_sizes; (void)n_in; (void)out_size;
    const float* beta  = (const float*)d_in[0];
    const float* embed = (const float*)d_in[1];
    const int*   sid   = (const int*)d_in[2];
    const int*   cp    = (const int*)d_in[3];

    pass_a_kernel<<<dim3(64, BB), 256>>>(beta, sid, cp);
    rep_prep_kernel<<<BB, 1024>>>(embed);
    fused_kernel<<<dim3(PB_BLOCKS + REP_BLOCKS, BB), 512>>>(embed, sid);
    finalize_kernel<<<1, 256>>>((float*)d_out);
}

// round 9
// speedup vs baseline: 1.0579x; 1.0579x over previous
#include <cuda_runtime.h>
#include <cstdint>

#define BB 8
#define NN 262144
#define KK 256
#define DD 16
#define CAP 2048
#define MMAX 1024
#define PB_BLOCKS 128          // pass_b blocks per event (2048 rows each)
#define REP_BLOCKS 16          // rep j-chunk blocks per event (scheduled FIRST)
#define RCH 64                 // rep j-chunk size

// ---------------- scratch (device globals; zero == reset state) ----------------
__device__ float  g_sum_f [BB][KK];
__device__ int    g_cnt_cp[BB][KK];
__device__ int    g_inst  [BB][KK];
__device__ int    g_first [BB][KK];   // stores max(NN - li); 0 == no CP
__device__ float  g_sd2   [BB][KK];
__device__ float4 g_anchor[BB][KK][4];
__device__ int    g_Mv    [BB];
__device__ int    g_cplist[BB][CAP];
__device__ float  g_scal_f[BB][4];    // 0: sum ce0*~cp, 1: sum ce0*bg, 2: pos_margin, 3: neg_margin
__device__ int    g_scal_i[BB][2];    // 0: n_cp(all), 1: n_bg
__device__ float  g_rep   [BB];
__device__ float4 g_cpemb [BB][MMAX * 4];

// fast sigmoid + softplus: 2 MUFU + FMA-pipe Newton rcp (seed valid on u in (1,2])
__device__ __forceinline__ void fast_sig_sp(float x, float& p, float& ce0) {
    const float t = __expf(-fabsf(x));
    const float u = 1.f + t;
    float y = __fmaf_rn(u, -0.47058824f, 1.4117647f);
    y = y * __fmaf_rn(-u, y, 2.f);
    y = y * __fmaf_rn(-u, y, 2.f);
    ce0 = fmaxf(x, 0.f) + __logf(u);
    p   = (x >= 0.f) ? y : t * y;
}

// ---------------- pass A: full prefetch (12 LDG.128 in flight), grid 64x8 ----------
__global__ void __launch_bounds__(256) pass_a_kernel(
    const float* __restrict__ beta,
    const int* __restrict__ sid,
    const int* __restrict__ cp)
{
    const int b   = blockIdx.y;
    const int tid = threadIdx.x;

    __shared__ float s_f[KK];
    __shared__ int   s_cnt[KK];
    __shared__ int   s_first[KK];
    __shared__ float s_sc[4];
    __shared__ int   s_si[2];

    s_f[tid] = 0.f; s_cnt[tid] = 0; s_first[tid] = 0;
    if (tid < 4) s_sc[tid] = 0.f;
    if (tid < 2) s_si[tid] = 0;
    __syncthreads();

    float ce0n = 0.f, bg = 0.f, pm = 0.f, nm = 0.f;
    int ncp = 0, nbg = 0;

    const size_t ev_base = (size_t)b * NN;
    const int blk_base = blockIdx.x * 4096;

    int4 s4[4], c4[4];
    float4 x4[4];
    #pragma unroll
    for (int it = 0; it < 4; it++) {
        const int li0 = blk_base + it * 1024 + tid * 4;
        s4[it] = *reinterpret_cast<const int4*>(sid + ev_base + li0);
        c4[it] = *reinterpret_cast<const int4*>(cp  + ev_base + li0);
        x4[it] = *reinterpret_cast<const float4*>(beta + ev_base + li0);
    }

    #pragma unroll
    for (int it = 0; it < 4; it++) {
        const int li0 = blk_base + it * 1024 + tid * 4;
        const int   sv[4] = {s4[it].x, s4[it].y, s4[it].z, s4[it].w};
        const int   cv[4] = {c4[it].x, c4[it].y, c4[it].z, c4[it].w};
        const float xv[4] = {x4[it].x, x4[it].y, x4[it].z, x4[it].w};

        #pragma unroll
        for (int j = 0; j < 4; j++) {
            const int   s = sv[j];
            const float x = xv[j];
            float p, ce0;
            fast_sig_sp(x, p, ce0);

            if (cv[j]) {
                ncp++;
                pm += fmaxf(0.8f - p, 0.f);
                if (s >= 0) {
                    const float om = 1.f - p;
                    atomicAdd(&s_f[s], 0.75f * om * om * (ce0 - x));
                    atomicAdd(&s_cnt[s], 1);
                    atomicMax(&s_first[s], NN - (li0 + j));
                    int pos = atomicAdd(&g_Mv[b], 1);
                    if (pos < CAP) g_cplist[b][pos] = li0 + j;
                }
            } else {
                ce0n += ce0;
                nm += fmaxf(p - 0.2f, 0.f);
            }
            if (s == -1) { nbg++; bg += ce0; }
        }
    }

    atomicAdd(&s_sc[0], ce0n);
    atomicAdd(&s_sc[1], bg);
    atomicAdd(&s_sc[2], pm);
    atomicAdd(&s_sc[3], nm);
    atomicAdd(&s_si[0], ncp);
    atomicAdd(&s_si[1], nbg);
    __syncthreads();

    if (s_f[tid] != 0.f) atomicAdd(&g_sum_f[b][tid], s_f[tid]);
    if (s_cnt[tid])      atomicAdd(&g_cnt_cp[b][tid], s_cnt[tid]);
    if (s_first[tid])    atomicMax(&g_first[b][tid], s_first[tid]);
    if (tid < 4) atomicAdd(&g_scal_f[b][tid], s_sc[tid]);
    if (tid < 2) atomicAdd(&g_scal_i[b][tid], s_si[tid]);
}

// ---------------- rep prep (+ anchor gather): one block per event ----------------
__global__ void __launch_bounds__(1024) rep_prep_kernel(const float* __restrict__ embed) {
    const int b   = blockIdx.x;
    const int tid = threadIdx.x;
    __shared__ int sidx[CAP];

    for (int t = tid; t < KK * 4; t += 1024) {
        const int q = t & 3, k = t >> 2;
        const int val = g_first[b][k];
        float4 v = make_float4(0.f, 0.f, 0.f, 0.f);
        if (val > 0) {
            const int fi = NN - val;
            v = reinterpret_cast<const float4*>(embed + ((size_t)b * NN + fi) * DD)[q];
        }
        g_anchor[b][k][q] = v;
    }

    const int Mv   = g_Mv[b];
    const int mcol = min(Mv, CAP);
    const int msel = min(Mv, MMAX);

    for (int i = tid; i < CAP; i += 1024)
        sidx[i] = (i < mcol) ? g_cplist[b][i] : 0x7fffffff;
    __syncthreads();

    if (Mv > MMAX) {   // statistically never; correctness fallback
        for (int ksz = 2; ksz <= CAP; ksz <<= 1) {
            for (int j = ksz >> 1; j > 0; j >>= 1) {
                for (int i = tid; i < CAP; i += 1024) {
                    int ixj = i ^ j;
                    if (ixj > i) {
                        bool up = ((i & ksz) == 0);
                        int a = sidx[i], c = sidx[ixj];
                        if ((a > c) == up) { sidx[i] = c; sidx[ixj] = a; }
                    }
                }
                __syncthreads();
            }
        }
    }

    for (int t = tid; t < msel * 4; t += 1024) {
        const int i = t >> 2, qq = t & 3;
        g_cpemb[b][i * 4 + qq] =
            reinterpret_cast<const float4*>(embed + ((size_t)b * NN + sidx[i]) * DD)[qq];
    }
}

// ---------------- fused: repulsion (bx<16) + pass_b (bx>=16), 256 thr ---------------
union FusedSmem {
    struct {
        float4             sA[KK][4];     // 16 KB
        unsigned long long spack[KK];     // 2 KB
        unsigned char      shc[KK];       // 256 B
    } pb;
    struct {
        float sj[RCH * DD];               // 4 KB
        float red[8];
    } rep;
};

__global__ void __launch_bounds__(256) fused_kernel(
    const float* __restrict__ embed,
    const int* __restrict__ sid)
{
    const int b   = blockIdx.y;
    const int tid = threadIdx.x;
    __shared__ FusedSmem sm;

    if (blockIdx.x >= REP_BLOCKS) {
        // ======== pass B: attraction + instance count (R7 body) ========
        #pragma unroll
        for (int i = tid; i < KK * 4; i += 256)
            sm.pb.sA[i >> 2][i & 3] = g_anchor[b][i >> 2][i & 3];
        if (tid < KK) {
            sm.pb.spack[tid] = 0ull;
            sm.pb.shc[tid] = (g_cnt_cp[b][tid] > 0) ? 1 : 0;
        }
        __syncthreads();

        const size_t ev_base = (size_t)b * NN;
        const int base = (blockIdx.x - REP_BLOCKS) * 2048 + tid;

        int sv[8];
        #pragma unroll
        for (int r = 0; r < 8; r++)
            sv[r] = sid[ev_base + base + r * 256];

        #pragma unroll 2
        for (int r = 0; r < 8; r++) {
            const int s = sv[r];
            if (s >= 0) {
                unsigned long long pack = 1ull << 44;
                if (sm.pb.shc[s]) {
                    const float4* e = reinterpret_cast<const float4*>(
                        embed + (ev_base + base + r * 256) * DD);
                    const float4 e0 = e[0], e1 = e[1], e2 = e[2], e3 = e[3];
                    const float4 a0 = sm.pb.sA[s][0], a1 = sm.pb.sA[s][1];
                    const float4 a2 = sm.pb.sA[s][2], a3 = sm.pb.sA[s][3];
                    float d2 = 0.f;
                    d2 = __fmaf_rn(e0.x - a0.x, e0.x - a0.x, d2);
                    d2 = __fmaf_rn(e0.y - a0.y, e0.y - a0.y, d2);
                    d2 = __fmaf_rn(e0.z - a0.z, e0.z - a0.z, d2);
                    d2 = __fmaf_rn(e0.w - a0.w, e0.w - a0.w, d2);
                    d2 = __fmaf_rn(e1.x - a1.x, e1.x - a1.x, d2);
                    d2 = __fmaf_rn(e1.y - a1.y, e1.y - a1.y, d2);
                    d2 = __fmaf_rn(e1.z - a1.z, e1.z - a1.z, d2);
                    d2 = __fmaf_rn(e1.w - a1.w, e1.w - a1.w, d2);
                    d2 = __fmaf_rn(e2.x - a2.x, e2.x - a2.x, d2);
                    d2 = __fmaf_rn(e2.y - a2.y, e2.y - a2.y, d2);
                    d2 = __fmaf_rn(e2.z - a2.z, e2.z - a2.z, d2);
                    d2 = __fmaf_rn(e2.w - a2.w, e2.w - a2.w, d2);
                    d2 = __fmaf_rn(e3.x - a3.x, e3.x - a3.x, d2);
                    d2 = __fmaf_rn(e3.y - a3.y, e3.y - a3.y, d2);
                    d2 = __fmaf_rn(e3.z - a3.z, e3.z - a3.z, d2);
                    d2 = __fmaf_rn(e3.w - a3.w, e3.w - a3.w, d2);
                    pack += __float2ull_rn(d2 * 1048576.f);
                }
                atomicAdd(&sm.pb.spack[s], pack);
            }
        }
        __syncthreads();
        if (tid < KK) {
            const unsigned long long v = sm.pb.spack[tid];
            if (v) {
                atomicAdd(&g_inst[b][tid], (int)(v >> 44));
                const float ds = (float)(v & ((1ull << 44) - 1ull)) * (1.f / 1048576.f);
                if (ds != 0.f) atomicAdd(&g_sd2[b][tid], ds);
            }
        }
    } else {
        // ======== repulsion: j-chunk blockIdx.x (R7 body) ========
        const int j0 = blockIdx.x * RCH;
        const int Mv   = g_Mv[b];
        const int msel = min(Mv, MMAX);
        if (j0 >= msel) return;                    // block-uniform
        const int cnt = min(RCH, msel - j0);

        for (int t = tid; t < cnt * 4; t += 256) {
            const int j = t >> 2, qq = t & 3;
            reinterpret_cast<float4*>(sm.rep.sj)[j * 4 + qq] = g_cpemb[b][(j0 + j) * 4 + qq];
        }
        __syncthreads();

        float acc = 0.f;
        for (int i = tid; i < msel; i += 256) {
            float myE[DD];
            #pragma unroll
            for (int qq = 0; qq < 4; qq++) {
                const float4 v = g_cpemb[b][i * 4 + qq];
                myE[qq * 4 + 0] = v.x; myE[qq * 4 + 1] = v.y;
                myE[qq * 4 + 2] = v.z; myE[qq * 4 + 3] = v.w;
            }
            #pragma unroll 2
            for (int j = 0; j < cnt; j++) {
                float d2 = 0.f;
                #pragma unroll
                for (int d = 0; d < DD; d++) {
                    const float df = myE[d] - sm.rep.sj[j * DD + d];
                    d2 = __fmaf_rn(df, df, d2);
                }
                acc += __expf(-d2);
            }
        }

        #pragma unroll
        for (int off = 16; off; off >>= 1) acc += __shfl_down_sync(0xffffffff, acc, off);
        if ((tid & 31) == 0) sm.rep.red[tid >> 5] = acc;
        __syncthreads();
        if (tid == 0) {
            float tot = 0.f;
            #pragma unroll
            for (int w = 0; w < 8; w++) tot += sm.rep.red[w];
            atomicAdd(&g_rep[b], tot);
        }
    }
}

// ---------------- finalize: one warp per event, parallel loads ----------------
__global__ void __launch_bounds__(256) finalize_kernel(float* __restrict__ out) {
    const int tid  = threadIdx.x;
    const int lane = tid & 31;
    const int b    = tid >> 5;               // warp b handles event b (8 warps = BB)

    __shared__ float s_loss[BB];
    __shared__ int   s_ok[BB];

    float w = 0.f, wf = 0.f, at = 0.f;
    #pragma unroll
    for (int k = lane; k < KK; k += 32) {
        const int c    = g_cnt_cp[b][k];
        const int inst = g_inst[b][k];
        if (c > 0) {
            const float fw = (float)inst;
            w  += fw;
            wf += fw * g_sum_f[b][k] / fmaxf((float)c, 1.f);
            at += g_sd2[b][k] / fmaxf((float)inst, 1.f);
        }
    }
    #pragma unroll
    for (int off = 16; off; off >>= 1) {
        w  += __shfl_down_sync(0xffffffff, w,  off);
        wf += __shfl_down_sync(0xffffffff, wf, off);
        at += __shfl_down_sync(0xffffffff, at, off);
    }

    if (lane == 0) {
        const float pos_bce = wf / fmaxf(w, 1.f);

        const float n_cp  = (float)g_scal_i[b][0];
        const float n_bg  = (float)g_scal_i[b][1];
        const float n_ncp = (float)NN - n_cp;
        const float n_val = (float)NN - n_bg;

        const float neg_bce    = (n_ncp > 0.f) ? g_scal_f[b][0] / fmaxf(n_ncp, 1.f) : 0.f;
        const float bg_bce     = (n_bg  > 0.f) ? g_scal_f[b][1] / fmaxf(n_bg,  1.f) : 0.f;
        const float pos_margin = g_scal_f[b][2] / fmaxf(n_cp, 1.f);
        const float neg_margin = (n_ncp > 0.f) ? g_scal_f[b][3] / fmaxf(n_ncp, 1.f) : 0.f;

        const float beta_loss = 10.f * pos_bce + 3.f * neg_bce + 6.f * bg_bce
                              + 10.f * (pos_margin + neg_margin);

        const int   Mv = g_Mv[b];
        const float fM = (float)Mv;
        const float rep_term = (Mv > 1) ? g_rep[b] / fmaxf(fM * fM, 1.f) : 0.f;

        s_loss[b] = beta_loss + at + rep_term;
        s_ok[b]   = (n_val > 0.f) && (Mv > 0);
    }
    __syncthreads();

    if (tid == 0) {
        float total = 0.f, cnt = 0.f;
        #pragma unroll
        for (int e = 0; e < BB; e++)
            if (s_ok[e]) { total += s_loss[e]; cnt += 1.f; }
        out[0] = (cnt > 0.f) ? total / fmaxf(cnt, 1.f) : 0.f;
    }

    // reset all scratch so the graph replays deterministically
    __syncthreads();
    #pragma unroll
    for (int e = 0; e < BB; e++) {
        g_sum_f[e][tid]  = 0.f;
        g_cnt_cp[e][tid] = 0;
        g_inst[e][tid]   = 0;
        g_first[e][tid]  = 0;
        g_sd2[e][tid]    = 0.f;
    }
    if (tid < BB) {
        g_Mv[tid]  = 0;
        g_rep[tid] = 0.f;
        #pragma unroll
        for (int j = 0; j < 4; j++) g_scal_f[tid][j] = 0.f;
        g_scal_i[tid][0] = 0; g_scal_i[tid][1] = 0;
    }
}

// ---------------- launch ----------------
extern "C" void kernel_launch(void* const* d_in, const int* in_sizes, int n_in,
                              void* d_out, int out_size)
{
    (void)in_sizes; (void)n_in; (void)out_size;
    const float* beta  = (const float*)d_in[0];
    const float* embed = (const float*)d_in[1];
    const int*   sid   = (const int*)d_in[2];
    const int*   cp    = (const int*)d_in[3];

    pass_a_kernel<<<dim3(64, BB), 256>>>(beta, sid, cp);
    rep_prep_kernel<<<BB, 1024>>>(embed);
    fused_kernel<<<dim3(REP_BLOCKS + PB_BLOCKS, BB), 256>>>(embed, sid);
    finalize_kernel<<<1, 256>>>((float*)d_out);
}